// round 16
// baseline (speedup 1.0000x reference)
#include <cuda_runtime.h>
#include <cstdint>

typedef unsigned long long u64;
typedef unsigned int u32;

#define ROWS 8192
#define KDIM 3072
#define NOUT 64
#define KT   128                // k per tile
#define NKT  24                 // 3072/128
#define RPC  64                 // rows per CTA
#define NCTA 128                // gemm CTAs
#define BSTAGE 32768            // B tile: 64 n x 128 k f32
#define NSTAGE 3
#define SMEMSZ (NSTAGE * BSTAGE)          // 98304
#define XW_SMEM (25600 + 9216 + 50176)    // 84992

// ---- scratch (no allocation allowed) ----
__device__ __align__(16) float g_xwt[8 * NOUT * KDIM];     // B matrices, tf32-rounded
__device__ __align__(16) float g_zbuf[ROWS * NOUT];
__device__ __align__(16) float g_part[NCTA * NOUT];        // [cta][k]
__device__ __align__(16) float g_psq [NCTA * NOUT];

// ---- helpers ----
__device__ __forceinline__ void cp16(char* smem_dst, const void* gsrc){
    unsigned s = (unsigned)__cvta_generic_to_shared(smem_dst);
    asm volatile("cp.async.cg.shared.global [%0], [%1], 16;" :: "r"(s), "l"(gsrc));
}
__device__ __forceinline__ u32 to_tf32(float f){
    u32 r; asm("cvt.rna.tf32.f32 %0,%1;" : "=r"(r) : "f"(f)); return r;
}
__device__ __forceinline__ void mma_tf32(float c[4], const u32 a[4], const u32 b[2]){
    asm volatile(
        "mma.sync.aligned.m16n8k8.row.col.f32.tf32.tf32.f32 "
        "{%0,%1,%2,%3}, {%4,%5,%6,%7}, {%8,%9}, {%0,%1,%2,%3};"
        : "+f"(c[0]), "+f"(c[1]), "+f"(c[2]), "+f"(c[3])
        : "r"(a[0]), "r"(a[1]), "r"(a[2]), "r"(a[3]), "r"(b[0]), "r"(b[1]));
}

// ============================================================================
// k_xw: XWT[b][n][m*3+j] = tf32( sum_f x[b,m,f] * Wc[n, j*32+f] )
// grid 128 = (b 8, mchunk 16), block 512 = (n 64, mq 8)  (R15, unchanged)
// ============================================================================
__global__ __launch_bounds__(512)
void k_xw(const float* __restrict__ x, const float* __restrict__ W1,
          const float* __restrict__ W2)
{
    extern __shared__ __align__(16) char xsm[];
    float4* ws4 = (float4*)xsm;                   // [64 n][25]
    float4* xs4 = (float4*)(xsm + 25600);         // [64 m][9]
    float*  stg = (float*)(xsm + 25600 + 9216);   // [64 n][196]
    const int bb = blockIdx.x >> 4;
    const int ch = blockIdx.x & 15;
    const int tid = threadIdx.x;

    for (int i = tid; i < 1536; i += 512) {
        int n = i / 24, c = i % 24;
        const float4* src = (n < 32) ? (const float4*)(W1 + n * 96)
                                     : (const float4*)(W2 + (size_t)(n - 32) * 96);
        ws4[n * 25 + c] = src[c];
    }
    {
        const float4* xb = (const float4*)(x + ((size_t)bb * 1024 + ch * 64) * 32);
        float4 v = xb[tid];
        int m = tid >> 3, fq = tid & 7;
        xs4[m * 9 + fq] = v;
    }
    __syncthreads();

    const int n = tid >> 3, mq = tid & 7;
    const float4* wn4 = ws4 + n * 25;
    #pragma unroll 1
    for (int mg = 0; mg < 2; mg++) {
        float a[4][3];
        #pragma unroll
        for (int mi = 0; mi < 4; mi++) { a[mi][0] = a[mi][1] = a[mi][2] = 0.f; }
        #pragma unroll
        for (int fq = 0; fq < 8; fq++) {
            float4 w0 = wn4[fq];
            float4 w1 = wn4[8 + fq];
            float4 w2 = wn4[16 + fq];
            #pragma unroll
            for (int mi = 0; mi < 4; mi++) {
                const int m = mq + 8 * (mg * 4 + mi);
                float4 xv = xs4[m * 9 + fq];
                a[mi][0] = fmaf(xv.x, w0.x, fmaf(xv.y, w0.y, fmaf(xv.z, w0.z, fmaf(xv.w, w0.w, a[mi][0]))));
                a[mi][1] = fmaf(xv.x, w1.x, fmaf(xv.y, w1.y, fmaf(xv.z, w1.z, fmaf(xv.w, w1.w, a[mi][1]))));
                a[mi][2] = fmaf(xv.x, w2.x, fmaf(xv.y, w2.y, fmaf(xv.z, w2.z, fmaf(xv.w, w2.w, a[mi][2]))));
            }
        }
        #pragma unroll
        for (int mi = 0; mi < 4; mi++) {
            const int m = mq + 8 * (mg * 4 + mi);
            stg[n * 196 + m * 3 + 0] = __uint_as_float(to_tf32(a[mi][0]));
            stg[n * 196 + m * 3 + 1] = __uint_as_float(to_tf32(a[mi][1]));
            stg[n * 196 + m * 3 + 2] = __uint_as_float(to_tf32(a[mi][2]));
        }
    }
    __syncthreads();

    float* outb = g_xwt + (size_t)bb * NOUT * KDIM + ch * 192;
    for (int i = tid; i < 3072; i += 512) {
        int nn = i / 48, c = i % 48;
        float4 v = *(const float4*)&stg[nn * 196 + c * 4];
        *(float4*)&outb[(size_t)nn * KDIM + c * 4] = v;
    }
}

// ============================================================================
// k_gemm: C[64,64] = A[64,3072] x B[64,3072]^T, A direct-from-global
// grid 128, block 512 = 4 M-warps x 4 s-groups; B double(triple)-buffered smem
// ============================================================================
__global__ __launch_bounds__(512, 1)
void k_gemm(const float* __restrict__ WW,
            const float* __restrict__ b1, const float* __restrict__ b2)
{
    extern __shared__ __align__(1024) char smem[];
    __shared__ float bias[64];
    __shared__ float ps[256], pq[256];
    const int tid  = threadIdx.x;
    const int warp = tid >> 5, lane = tid & 31;
    const int mw   = warp & 3;          // M-warp: rows mw*16 .. +15
    const int sg   = warp >> 2;         // s-group 0..3: s = sg*4 + si
    const int g    = lane >> 2, t4 = lane & 3;
    const int R0   = blockIdx.x * RPC;
    const int bb   = blockIdx.x >> 4;   // 16 CTAs per batch

    if (tid < 32)       bias[tid] = b1[tid];
    else if (tid < 64)  bias[tid] = b2[tid - 32];

    float acc[8][4];
    #pragma unroll
    for (int nt = 0; nt < 8; nt++)
        #pragma unroll
        for (int i = 0; i < 4; i++) acc[nt][i] = 0.f;

    // A direct-LDG pointers: fragment lane (g, t4); rows mw*16+g and +8
    const float* p0 = WW + (size_t)(R0 + mw * 16 + g) * KDIM + t4;      // row g,  k t4
    const float* p1 = p0 + (size_t)8 * KDIM;                            // row g+8
    const float* Bbase = g_xwt + (size_t)bb * NOUT * KDIM;

    auto issueB = [&](int t){
        char* sb = smem + (t % NSTAGE) * BSTAGE;
        const int k0 = t * KT;
        #pragma unroll
        for (int i = 0; i < 4; i++) {
            int c = tid + i * 512;                 // < 2048
            int rr = c >> 5, cq = c & 31;
            cp16(sb + rr * 512 + ((cq ^ (rr & 7)) << 4),
                 Bbase + (size_t)rr * KDIM + k0 + cq * 4);
        }
        asm volatile("cp.async.commit_group;" ::: "memory");
    };

    issueB(0); issueB(1);

    // prime A prefetch ring: pf[si] holds k-block kb = t*16 + sg*4 + si
    float4 pf[4];
    #pragma unroll
    for (int si = 0; si < 4; si++) {
        const int kb = sg * 4 + si;
        pf[si].x = p0[kb * 8];     pf[si].y = p1[kb * 8];
        pf[si].z = p0[kb * 8 + 4]; pf[si].w = p1[kb * 8 + 4];
    }

    #pragma unroll 1
    for (int t = 0; t < NKT; t++) {
        if (t + 1 < NKT) asm volatile("cp.async.wait_group 1;" ::: "memory");
        else             asm volatile("cp.async.wait_group 0;" ::: "memory");
        __syncthreads();
        if (t + 2 < NKT) issueB(t + 2);

        const u32* Bs = (const u32*)(smem + (t % NSTAGE) * BSTAGE);
        const int tn = (t + 1 < NKT) ? (t + 1) : t;   // clamp (redundant last loads)

        #pragma unroll
        for (int si = 0; si < 4; si++) {
            const int s = sg * 4 + si;                  // 0..15
            float4 av = pf[si];
            {   // prefetch next tile's same slot
                const int kb = tn * 16 + sg * 4 + si;
                pf[si].x = p0[kb * 8];     pf[si].y = p1[kb * 8];
                pf[si].z = p0[kb * 8 + 4]; pf[si].w = p1[kb * 8 + 4];
            }
            u32 a[4];
            a[0] = to_tf32(av.x); a[1] = to_tf32(av.y);
            a[2] = to_tf32(av.z); a[3] = to_tf32(av.w);
            const int c0 = ((2 * s)     ^ g) * 4 + t4;
            const int c1 = ((2 * s + 1) ^ g) * 4 + t4;
            u32 b[8][2];
            #pragma unroll
            for (int nt = 0; nt < 8; nt++) {
                const int nb = (nt * 8 + g) * 128;
                b[nt][0] = Bs[nb + c0];
                b[nt][1] = Bs[nb + c1];
            }
            #pragma unroll
            for (int nt = 0; nt < 8; nt++)
                mma_tf32(acc[nt], a, b[nt]);
        }
    }

    // ---- tree-merge 4 s-groups through smem ----
    __syncthreads();                                  // all B stages consumed
    const int sl = tid & 127;                         // (mw, lane) slot
    float4* av4 = (float4*)&acc[0][0];                // 8 float4
    auto region = [&](int rgn)->float4* { return (float4*)(smem + rgn * 18432); };

    if (sg >= 2) { float4* bf = region(sg - 2);
        for (int i = 0; i < 8; i++) bf[sl * 9 + i] = av4[i]; }
    __syncthreads();
    if (sg < 2)  { float4* bf = region(sg);
        for (int i = 0; i < 8; i++) { float4 o = bf[sl * 9 + i];
            av4[i].x += o.x; av4[i].y += o.y; av4[i].z += o.z; av4[i].w += o.w; } }
    __syncthreads();
    if (sg == 1) { float4* bf = region(0);
        for (int i = 0; i < 8; i++) bf[sl * 9 + i] = av4[i]; }
    __syncthreads();

    // ---- sg0 (128 threads) finalizes: bias + relu + zbuf + zs ----
    float* zs = (float*)(smem + 40960);               // 64 x 66 floats
    if (sg == 0) {
        float4* bf = region(0);
        for (int i = 0; i < 8; i++) { float4 o = bf[sl * 9 + i];
            av4[i].x += o.x; av4[i].y += o.y; av4[i].z += o.z; av4[i].w += o.w; }
        const int r0 = mw * 16 + g;                   // and r0+8
        #pragma unroll
        for (int nt = 0; nt < 8; nt++) {
            const int col = nt * 8 + 2 * t4;
            float z0 = acc[nt][0] + bias[col];
            float z1 = acc[nt][1] + bias[col + 1];
            float z2 = acc[nt][2] + bias[col];
            float z3 = acc[nt][3] + bias[col + 1];
            if (nt < 4) { z0 = fmaxf(z0, 0.f); z1 = fmaxf(z1, 0.f);
                          z2 = fmaxf(z2, 0.f); z3 = fmaxf(z3, 0.f); }
            *(float2*)&g_zbuf[(size_t)(R0 + r0) * 64 + col]     = make_float2(z0, z1);
            *(float2*)&g_zbuf[(size_t)(R0 + r0 + 8) * 64 + col] = make_float2(z2, z3);
            zs[r0 * 66 + col] = z0; zs[r0 * 66 + col + 1] = z1;
            zs[(r0 + 8) * 66 + col] = z2; zs[(r0 + 8) * 66 + col + 1] = z3;
        }
    }
    __syncthreads();

    // ---- BN partials over this CTA's 64 rows ----
    if (tid < 256) {
        const int k = tid & 63, qd = tid >> 6;
        float s = 0.f, sq = 0.f;
        #pragma unroll
        for (int r = qd * 16; r < qd * 16 + 16; r++) {
            float v = zs[r * 66 + k];
            s += v; sq += v * v;
        }
        ps[tid] = s; pq[tid] = sq;
    }
    __syncthreads();
    if (tid < 64) {
        g_part[blockIdx.x * 64 + tid] = ps[tid] + ps[64 + tid] + ps[128 + tid] + ps[192 + tid];
        g_psq [blockIdx.x * 64 + tid] = pq[tid] + pq[64 + tid] + pq[128 + tid] + pq[192 + tid];
    }
}

// ============================================================================
// k_norm: redundant per-block stats + normalize; grid 256 (R15, unchanged)
// ============================================================================
__global__ __launch_bounds__(256)
void k_norm(const float* __restrict__ gamma, const float* __restrict__ beta,
            float* __restrict__ out)
{
    __shared__ float sc[64], sh[64];
    __shared__ float rs[256], rq[256];
    const int tid = threadIdx.x;
    {
        const int k = tid & 63, qd = tid >> 6;
        float s = 0.f, sq = 0.f;
        #pragma unroll 8
        for (int c = qd * 32; c < qd * 32 + 32; c++) {
            s  += g_part[c * 64 + k];
            sq += g_psq [c * 64 + k];
        }
        rs[tid] = s; rq[tid] = sq;
    }
    __syncthreads();
    if (tid < 64) {
        float s  = rs[tid] + rs[64 + tid] + rs[128 + tid] + rs[192 + tid];
        float sq = rq[tid] + rq[64 + tid] + rq[128 + tid] + rq[192 + tid];
        float mean = s / (float)ROWS;
        float var  = sq / (float)ROWS - mean * mean;
        float scale = gamma[tid] * rsqrtf(var + 1e-5f);
        sc[tid] = scale;
        sh[tid] = beta[tid] - mean * scale;
    }
    __syncthreads();
    #pragma unroll
    for (int it = 0; it < 2; it++) {
        int i = blockIdx.x * 512 + it * 256 + tid;
        float4 z = ((const float4*)g_zbuf)[i];
        int kb = (i & 15) * 4;
        float4 o;
        o.x = z.x * sc[kb+0] + sh[kb+0];
        o.y = z.y * sc[kb+1] + sh[kb+1];
        o.z = z.z * sc[kb+2] + sh[kb+2];
        o.w = z.w * sc[kb+3] + sh[kb+3];
        ((float4*)out)[i] = o;
    }
}

extern "C" void kernel_launch(void* const* d_in, const int* in_sizes, int n_in,
                              void* d_out, int out_size)
{
    const float* WW    = (const float*)d_in[0];
    const float* x     = (const float*)d_in[1];
    const float* W1    = (const float*)d_in[2];
    const float* b1    = (const float*)d_in[3];
    const float* W2    = (const float*)d_in[4];
    const float* b2    = (const float*)d_in[5];
    const float* gamma = (const float*)d_in[6];
    const float* beta  = (const float*)d_in[7];
    float* out = (float*)d_out;

    cudaFuncSetAttribute(k_xw,   cudaFuncAttributeMaxDynamicSharedMemorySize, XW_SMEM);
    cudaFuncSetAttribute(k_gemm, cudaFuncAttributeMaxDynamicSharedMemorySize, SMEMSZ);

    k_xw   <<<128, 512, XW_SMEM>>>(x, W1, W2);
    k_gemm <<<NCTA, 512, SMEMSZ>>>(WW, b1, b2);
    k_norm <<<256, 256>>>(gamma, beta, out);
}

// round 17
// speedup vs baseline: 1.6810x; 1.6810x over previous
#include <cuda_runtime.h>
#include <cstdint>

typedef unsigned long long u64;
typedef unsigned int u32;

#define ROWS 8192
#define KDIM 3072
#define NOUT 64
#define KT   128                // k per tile
#define NKT  24                 // 3072/128
#define RPC  64                 // rows per CTA
#define NCTA 128                // gemm CTAs
#define STAGE_A 32768           // 64 rows * 128 f32
#define STAGE_B 32768           // 64 rows * 128 f32
#define STAGE   (STAGE_A + STAGE_B)
#define NSTAGE  3
#define SMEMSZ  (NSTAGE * STAGE)   // 196608
#define XW_SMEM (25600 + 9216 + 50176)   // 84992

// ---- scratch (no allocation allowed) ----
__device__ __align__(16) float g_xwt[8 * NOUT * KDIM];     // B matrices, tf32-rounded
__device__ __align__(16) float g_zbuf[ROWS * NOUT];
__device__ __align__(16) float g_part[NCTA * NOUT];        // [cta][k]
__device__ __align__(16) float g_psq [NCTA * NOUT];

// ---- helpers ----
__device__ __forceinline__ void cp16(char* smem_dst, const void* gsrc){
    unsigned s = (unsigned)__cvta_generic_to_shared(smem_dst);
    asm volatile("cp.async.cg.shared.global [%0], [%1], 16;" :: "r"(s), "l"(gsrc));
}
__device__ __forceinline__ u32 to_tf32(float f){
    u32 r; asm("cvt.rna.tf32.f32 %0,%1;" : "=r"(r) : "f"(f)); return r;
}
__device__ __forceinline__ void mma_tf32(float c[4], const u32 a[4], const u32 b[2]){
    asm volatile(
        "mma.sync.aligned.m16n8k8.row.col.f32.tf32.tf32.f32 "
        "{%0,%1,%2,%3}, {%4,%5,%6,%7}, {%8,%9}, {%0,%1,%2,%3};"
        : "+f"(c[0]), "+f"(c[1]), "+f"(c[2]), "+f"(c[3])
        : "r"(a[0]), "r"(a[1]), "r"(a[2]), "r"(a[3]), "r"(b[0]), "r"(b[1]));
}

// ============================================================================
// k_xw: XWT[b][n][m*3+j] = tf32( sum_f x[b,m,f] * Wc[n, j*32+f] )
// grid 128 = (b 8, mchunk 16), block 512 = (n 64, mq 8)  (R15, unchanged)
// ============================================================================
__global__ __launch_bounds__(512)
void k_xw(const float* __restrict__ x, const float* __restrict__ W1,
          const float* __restrict__ W2)
{
    extern __shared__ __align__(16) char xsm[];
    float4* ws4 = (float4*)xsm;                   // [64 n][25]
    float4* xs4 = (float4*)(xsm + 25600);         // [64 m][9]
    float*  stg = (float*)(xsm + 25600 + 9216);   // [64 n][196]
    const int bb = blockIdx.x >> 4;
    const int ch = blockIdx.x & 15;
    const int tid = threadIdx.x;

    for (int i = tid; i < 1536; i += 512) {
        int n = i / 24, c = i % 24;
        const float4* src = (n < 32) ? (const float4*)(W1 + n * 96)
                                     : (const float4*)(W2 + (size_t)(n - 32) * 96);
        ws4[n * 25 + c] = src[c];
    }
    {
        const float4* xb = (const float4*)(x + ((size_t)bb * 1024 + ch * 64) * 32);
        float4 v = xb[tid];
        int m = tid >> 3, fq = tid & 7;
        xs4[m * 9 + fq] = v;
    }
    __syncthreads();

    const int n = tid >> 3, mq = tid & 7;
    const float4* wn4 = ws4 + n * 25;
    #pragma unroll 1
    for (int mg = 0; mg < 2; mg++) {
        float a[4][3];
        #pragma unroll
        for (int mi = 0; mi < 4; mi++) { a[mi][0] = a[mi][1] = a[mi][2] = 0.f; }
        #pragma unroll
        for (int fq = 0; fq < 8; fq++) {
            float4 w0 = wn4[fq];
            float4 w1 = wn4[8 + fq];
            float4 w2 = wn4[16 + fq];
            #pragma unroll
            for (int mi = 0; mi < 4; mi++) {
                const int m = mq + 8 * (mg * 4 + mi);
                float4 xv = xs4[m * 9 + fq];
                a[mi][0] = fmaf(xv.x, w0.x, fmaf(xv.y, w0.y, fmaf(xv.z, w0.z, fmaf(xv.w, w0.w, a[mi][0]))));
                a[mi][1] = fmaf(xv.x, w1.x, fmaf(xv.y, w1.y, fmaf(xv.z, w1.z, fmaf(xv.w, w1.w, a[mi][1]))));
                a[mi][2] = fmaf(xv.x, w2.x, fmaf(xv.y, w2.y, fmaf(xv.z, w2.z, fmaf(xv.w, w2.w, a[mi][2]))));
            }
        }
        #pragma unroll
        for (int mi = 0; mi < 4; mi++) {
            const int m = mq + 8 * (mg * 4 + mi);
            stg[n * 196 + m * 3 + 0] = __uint_as_float(to_tf32(a[mi][0]));
            stg[n * 196 + m * 3 + 1] = __uint_as_float(to_tf32(a[mi][1]));
            stg[n * 196 + m * 3 + 2] = __uint_as_float(to_tf32(a[mi][2]));
        }
    }
    __syncthreads();

    float* outb = g_xwt + (size_t)bb * NOUT * KDIM + ch * 192;
    for (int i = tid; i < 3072; i += 512) {
        int nn = i / 48, c = i % 48;
        float4 v = *(const float4*)&stg[nn * 196 + c * 4];
        *(float4*)&outb[(size_t)nn * KDIM + c * 4] = v;
    }
}

// ============================================================================
// k_gemm: C[64,64] = A[64,3072] x B[64,3072]^T (tf32 mma.sync), fused epilogue
// grid 128, block 512 = 2 M-warps x 8 s-groups
// (R15 base; b-fragments consumed in two nt-halves to cut live registers)
// ============================================================================
__global__ __launch_bounds__(512, 1)
void k_gemm(const float* __restrict__ WW,
            const float* __restrict__ b1, const float* __restrict__ b2)
{
    extern __shared__ __align__(1024) char smem[];
    __shared__ float bias[64];
    __shared__ float ps[256], pq[256];
    const int tid  = threadIdx.x;
    const int warp = tid >> 5, lane = tid & 31;
    const int w2   = warp & 1;          // M-warp: rows w2*32 .. +31
    const int sg   = warp >> 1;         // s-group 0..7: s = 2*sg, 2*sg+1
    const int g    = lane >> 2, t4 = lane & 3;
    const int R0   = blockIdx.x * RPC;
    const int bb   = blockIdx.x >> 4;   // 16 CTAs per batch

    if (tid < 32)       bias[tid] = b1[tid];
    else if (tid < 64)  bias[tid] = b2[tid - 32];

    float acc[2][8][4];
    #pragma unroll
    for (int mt = 0; mt < 2; mt++)
        #pragma unroll
        for (int nt = 0; nt < 8; nt++)
            #pragma unroll
            for (int i = 0; i < 4; i++) acc[mt][nt][i] = 0.f;

    const float* Abase = WW + (size_t)R0 * KDIM;
    const float* Bbase = g_xwt + (size_t)bb * NOUT * KDIM;

    auto issue = [&](int t){
        char* sa = smem + (t % NSTAGE) * STAGE;
        char* sb = sa + STAGE_A;
        const int k0 = t * KT;
        #pragma unroll
        for (int i = 0; i < 4; i++) {
            int c = tid + i * 512;                 // < 2048
            int rr = c >> 5, cq = c & 31;
            cp16(sa + rr * 512 + ((cq ^ (rr & 7)) << 4),
                 Abase + (size_t)rr * KDIM + k0 + cq * 4);
        }
        #pragma unroll
        for (int i = 0; i < 4; i++) {
            int c = tid + i * 512;                 // < 2048
            int rr = c >> 5, cq = c & 31;
            cp16(sb + rr * 512 + ((cq ^ (rr & 7)) << 4),
                 Bbase + (size_t)rr * KDIM + k0 + cq * 4);
        }
        asm volatile("cp.async.commit_group;" ::: "memory");
    };

    issue(0); issue(1);

    #pragma unroll 1
    for (int t = 0; t < NKT; t++) {
        if (t + 1 < NKT) asm volatile("cp.async.wait_group 1;" ::: "memory");
        else             asm volatile("cp.async.wait_group 0;" ::: "memory");
        __syncthreads();
        if (t + 2 < NKT) issue(t + 2);

        const float* As = (const float*)(smem + (t % NSTAGE) * STAGE);
        const u32*   Bs = (const u32*)  (smem + (t % NSTAGE) * STAGE + STAGE_A);

        #pragma unroll
        for (int si = 0; si < 2; si++) {
            const int s  = sg * 2 + si;                 // 0..15
            const int c0 = ((2 * s)     ^ g) * 4 + t4;
            const int c1 = ((2 * s + 1) ^ g) * 4 + t4;
            u32 a[2][4];
            #pragma unroll
            for (int mt = 0; mt < 2; mt++) {
                const int ro = (w2 * 32 + mt * 16 + g) * 128;
                a[mt][0] = to_tf32(As[ro + c0]);
                a[mt][1] = to_tf32(As[ro + 1024 + c0]);
                a[mt][2] = to_tf32(As[ro + c1]);
                a[mt][3] = to_tf32(As[ro + 1024 + c1]);
            }
            // half 1: nt 0..3
            #pragma unroll
            for (int h = 0; h < 2; h++) {
                u32 b[4][2];
                #pragma unroll
                for (int q = 0; q < 4; q++) {
                    const int nt = h * 4 + q;
                    const int nb = (nt * 8 + g) * 128;
                    b[q][0] = Bs[nb + c0];
                    b[q][1] = Bs[nb + c1];
                }
                #pragma unroll
                for (int mt = 0; mt < 2; mt++)
                    #pragma unroll
                    for (int q = 0; q < 4; q++)
                        mma_tf32(acc[mt][h * 4 + q], a[mt], b[q]);
            }
        }
    }

    // ---- tree-merge 8 s-groups through smem ----
    __syncthreads();
    const int sl = tid & 63;
    float4* av = (float4*)&acc[0][0][0];
    auto region = [&](int rgn)->float4* { return (float4*)smem + rgn * 1088; };

    if (sg >= 4) { float4* bf = region(sg - 4);
        for (int i = 0; i < 16; i++) bf[sl * 17 + i] = av[i]; }
    __syncthreads();
    if (sg < 4)  { float4* bf = region(sg);
        for (int i = 0; i < 16; i++) { float4 o = bf[sl * 17 + i];
            av[i].x += o.x; av[i].y += o.y; av[i].z += o.z; av[i].w += o.w; } }
    __syncthreads();
    if (sg == 2 || sg == 3) { float4* bf = region(sg - 2);
        for (int i = 0; i < 16; i++) bf[sl * 17 + i] = av[i]; }
    __syncthreads();
    if (sg < 2)  { float4* bf = region(sg);
        for (int i = 0; i < 16; i++) { float4 o = bf[sl * 17 + i];
            av[i].x += o.x; av[i].y += o.y; av[i].z += o.z; av[i].w += o.w; } }
    __syncthreads();
    if (sg == 1) { float4* bf = region(0);
        for (int i = 0; i < 16; i++) bf[sl * 17 + i] = av[i]; }
    __syncthreads();

    // ---- sg0 (64 threads) finalizes: bias + relu + zbuf + zs ----
    float* zs = (float*)(smem + 72704);              // 64 x 66 floats
    if (sg == 0) {
        float4* bf = region(0);
        for (int i = 0; i < 16; i++) { float4 o = bf[sl * 17 + i];
            av[i].x += o.x; av[i].y += o.y; av[i].z += o.z; av[i].w += o.w; }
        #pragma unroll
        for (int mt = 0; mt < 2; mt++) {
            const int r0 = w2 * 32 + mt * 16 + g;
            #pragma unroll
            for (int nt = 0; nt < 8; nt++) {
                const int col = nt * 8 + 2 * t4;
                float z0 = acc[mt][nt][0] + bias[col];
                float z1 = acc[mt][nt][1] + bias[col + 1];
                float z2 = acc[mt][nt][2] + bias[col];
                float z3 = acc[mt][nt][3] + bias[col + 1];
                if (nt < 4) { z0 = fmaxf(z0, 0.f); z1 = fmaxf(z1, 0.f);
                              z2 = fmaxf(z2, 0.f); z3 = fmaxf(z3, 0.f); }
                *(float2*)&g_zbuf[(size_t)(R0 + r0) * 64 + col]     = make_float2(z0, z1);
                *(float2*)&g_zbuf[(size_t)(R0 + r0 + 8) * 64 + col] = make_float2(z2, z3);
                zs[r0 * 66 + col] = z0; zs[r0 * 66 + col + 1] = z1;
                zs[(r0 + 8) * 66 + col] = z2; zs[(r0 + 8) * 66 + col + 1] = z3;
            }
        }
    }
    __syncthreads();

    // ---- BN partials over this CTA's 64 rows ----
    if (tid < 256) {
        const int k = tid & 63, qd = tid >> 6;
        float s = 0.f, sq = 0.f;
        #pragma unroll
        for (int r = qd * 16; r < qd * 16 + 16; r++) {
            float v = zs[r * 66 + k];
            s += v; sq += v * v;
        }
        ps[tid] = s; pq[tid] = sq;
    }
    __syncthreads();
    if (tid < 64) {
        g_part[blockIdx.x * 64 + tid] = ps[tid] + ps[64 + tid] + ps[128 + tid] + ps[192 + tid];
        g_psq [blockIdx.x * 64 + tid] = pq[tid] + pq[64 + tid] + pq[128 + tid] + pq[192 + tid];
    }
}

// ============================================================================
// k_norm: redundant per-block stats + normalize; grid 256 (R15, unchanged)
// ============================================================================
__global__ __launch_bounds__(256)
void k_norm(const float* __restrict__ gamma, const float* __restrict__ beta,
            float* __restrict__ out)
{
    __shared__ float sc[64], sh[64];
    __shared__ float rs[256], rq[256];
    const int tid = threadIdx.x;
    {
        const int k = tid & 63, qd = tid >> 6;
        float s = 0.f, sq = 0.f;
        #pragma unroll 8
        for (int c = qd * 32; c < qd * 32 + 32; c++) {
            s  += g_part[c * 64 + k];
            sq += g_psq [c * 64 + k];
        }
        rs[tid] = s; rq[tid] = sq;
    }
    __syncthreads();
    if (tid < 64) {
        float s  = rs[tid] + rs[64 + tid] + rs[128 + tid] + rs[192 + tid];
        float sq = rq[tid] + rq[64 + tid] + rq[128 + tid] + rq[192 + tid];
        float mean = s / (float)ROWS;
        float var  = sq / (float)ROWS - mean * mean;
        float scale = gamma[tid] * rsqrtf(var + 1e-5f);
        sc[tid] = scale;
        sh[tid] = beta[tid] - mean * scale;
    }
    __syncthreads();
    #pragma unroll
    for (int it = 0; it < 2; it++) {
        int i = blockIdx.x * 512 + it * 256 + tid;
        float4 z = ((const float4*)g_zbuf)[i];
        int kb = (i & 15) * 4;
        float4 o;
        o.x = z.x * sc[kb+0] + sh[kb+0];
        o.y = z.y * sc[kb+1] + sh[kb+1];
        o.z = z.z * sc[kb+2] + sh[kb+2];
        o.w = z.w * sc[kb+3] + sh[kb+3];
        ((float4*)out)[i] = o;
    }
}

extern "C" void kernel_launch(void* const* d_in, const int* in_sizes, int n_in,
                              void* d_out, int out_size)
{
    const float* WW    = (const float*)d_in[0];
    const float* x     = (const float*)d_in[1];
    const float* W1    = (const float*)d_in[2];
    const float* b1    = (const float*)d_in[3];
    const float* W2    = (const float*)d_in[4];
    const float* b2    = (const float*)d_in[5];
    const float* gamma = (const float*)d_in[6];
    const float* beta  = (const float*)d_in[7];
    float* out = (float*)d_out;

    cudaFuncSetAttribute(k_xw,   cudaFuncAttributeMaxDynamicSharedMemorySize, XW_SMEM);
    cudaFuncSetAttribute(k_gemm, cudaFuncAttributeMaxDynamicSharedMemorySize, SMEMSZ);

    k_xw   <<<128, 512, XW_SMEM>>>(x, W1, W2);
    k_gemm <<<NCTA, 512, SMEMSZ>>>(WW, b1, b2);
    k_norm <<<256, 256>>>(gamma, beta, out);
}